// round 2
// baseline (speedup 1.0000x reference)
#include <cuda_runtime.h>
#include <math.h>

#define B_ 8
#define L_ 1024
#define D_ 512
#define H_ 8
#define DH_ 64
#define INNER_ 512
#define BH_ (B_*H_)

// ---------------- scratch (device globals; no runtime allocation) ----------------
__device__ float g_xn [B_*L_*D_];        // layernorm output            16 MB
__device__ float g_pe [L_*D_];           // rel-pos sinusoid table       2 MB
__device__ float g_pos[H_*L_*DH_];       // pos = pe @ w_pos^T (H,L,Dh)  2 MB
__device__ float g_q  [B_*H_*L_*DH_];    // q  (B,H,L,Dh)               16 MB
__device__ float g_k  [B_*H_*L_*DH_];    // k, later kplus = k+pos      16 MB
__device__ float g_v  [B_*H_*L_*DH_];    // v                           16 MB
__device__ float g_c  [B_*H_*L_];        // c[b,h,m] = u.k + v.pos     256 KB
__device__ float g_ctx[B_*L_*D_];        // attention context (B,L,HD)  16 MB

// ---------------- LayerNorm: one block per (b,l) row ----------------
__global__ void __launch_bounds__(128) ln_kernel(const float* __restrict__ x,
                                                 const float* __restrict__ gamma,
                                                 const float* __restrict__ beta)
{
    int row = blockIdx.x;                 // b*L + l
    int tid = threadIdx.x;                // 128 threads, 4 floats each
    const float4* xr = (const float4*)(x + (size_t)row * D_);
    float4 xv = xr[tid];
    float s  = xv.x + xv.y + xv.z + xv.w;
    float sq = xv.x*xv.x + xv.y*xv.y + xv.z*xv.z + xv.w*xv.w;
    #pragma unroll
    for (int o = 16; o > 0; o >>= 1) {
        s  += __shfl_xor_sync(0xffffffffu, s,  o);
        sq += __shfl_xor_sync(0xffffffffu, sq, o);
    }
    __shared__ float ss[4], ssq[4];
    int warp = tid >> 5, lane = tid & 31;
    if (lane == 0) { ss[warp] = s; ssq[warp] = sq; }
    __syncthreads();
    s  = ss[0] + ss[1] + ss[2] + ss[3];
    sq = ssq[0] + ssq[1] + ssq[2] + ssq[3];
    float mu   = s * (1.0f / D_);
    float var  = sq * (1.0f / D_) - mu * mu;
    float rstd = rsqrtf(var + 1e-5f);
    float4 g  = ((const float4*)gamma)[tid];
    float4 bb = ((const float4*)beta)[tid];
    float4 o;
    o.x = (xv.x - mu) * rstd * g.x + bb.x;
    o.y = (xv.y - mu) * rstd * g.y + bb.y;
    o.z = (xv.z - mu) * rstd * g.z + bb.z;
    o.w = (xv.w - mu) * rstd * g.w + bb.w;
    ((float4*)(g_xn + (size_t)row * D_))[tid] = o;
}

// ---------------- rel-pos sinusoid table pe[l][d] ----------------
__global__ void pe_kernel()
{
    int l = blockIdx.x;
    for (int d = threadIdx.x; d < D_; d += blockDim.x) {
        float freq  = __expf(-(float)(2 * d) * (9.210340371976184f / (float)D_));
        float angle = ((float)l - (float)d) * freq;          // fp32, matching reference
        double a = (double)angle;                            // accurate range reduction
        float val = ((d & 1) == 0) ? (float)cos(a) : (float)sin(a);
        g_pe[(size_t)l * D_ + d] = val;
    }
}

// ---------------- generic SGEMM: C = A @ W^T (+bias), 128x128x8 tiles ----------------
// MODE 0: OUT  : A=g_ctx, write C (d_out) row-major + bias
// MODE 1: POS  : A=g_pe,  write g_pos[(h,l,dh)]
// MODE 2: QKV  : A=g_xn,  split into g_q/g_k/g_v[(b,h,l,dh)] + bias
template<int MODE>
__global__ void __launch_bounds__(256) gemm_kernel(const float* __restrict__ W,
                                                   const float* __restrict__ bias,
                                                   float* __restrict__ C,
                                                   int M, int N, int K)
{
    const float* A = (MODE == 1) ? g_pe : (MODE == 2) ? g_xn : g_ctx;

    __shared__ float As[8 * 132];
    __shared__ float Bs[8 * 132];
    int tid = threadIdx.x;
    int tx = tid & 15, ty = tid >> 4;
    int m0 = blockIdx.y * 128, n0 = blockIdx.x * 128;

    int la_row = tid >> 1;            // 0..127
    int la_k   = (tid & 1) * 4;       // 0 or 4
    const float* Aptr = A + (size_t)(m0 + la_row) * K + la_k;
    const float* Wptr = W + (size_t)(n0 + la_row) * K + la_k;

    float acc[8][8];
    #pragma unroll
    for (int i = 0; i < 8; i++)
        #pragma unroll
        for (int j = 0; j < 8; j++) acc[i][j] = 0.0f;

    // prefetch first K-tile into registers
    float4 a4 = *(const float4*)(Aptr);
    float4 w4 = *(const float4*)(Wptr);

    for (int kt = 0; kt < K; kt += 8) {
        __syncthreads();
        As[(la_k + 0) * 132 + la_row] = a4.x;
        As[(la_k + 1) * 132 + la_row] = a4.y;
        As[(la_k + 2) * 132 + la_row] = a4.z;
        As[(la_k + 3) * 132 + la_row] = a4.w;
        Bs[(la_k + 0) * 132 + la_row] = w4.x;
        Bs[(la_k + 1) * 132 + la_row] = w4.y;
        Bs[(la_k + 2) * 132 + la_row] = w4.z;
        Bs[(la_k + 3) * 132 + la_row] = w4.w;
        __syncthreads();
        // prefetch next K-tile while computing this one (hides L2/DRAM latency)
        if (kt + 8 < K) {
            a4 = *(const float4*)(Aptr + kt + 8);
            w4 = *(const float4*)(Wptr + kt + 8);
        }
        #pragma unroll
        for (int k = 0; k < 8; k++) {
            float4 a0 = *(const float4*)&As[k * 132 + ty * 8];
            float4 a1 = *(const float4*)&As[k * 132 + ty * 8 + 4];
            float4 b0 = *(const float4*)&Bs[k * 132 + tx * 8];
            float4 b1 = *(const float4*)&Bs[k * 132 + tx * 8 + 4];
            float a[8] = {a0.x, a0.y, a0.z, a0.w, a1.x, a1.y, a1.z, a1.w};
            float b[8] = {b0.x, b0.y, b0.z, b0.w, b1.x, b1.y, b1.z, b1.w};
            #pragma unroll
            for (int i = 0; i < 8; i++)
                #pragma unroll
                for (int j = 0; j < 8; j++)
                    acc[i][j] += a[i] * b[j];
        }
    }

    int n_base = n0 + tx * 8;
    if (MODE == 0) {
        float bb[8];
        #pragma unroll
        for (int j = 0; j < 8; j++) bb[j] = bias[n_base + j];
        #pragma unroll
        for (int i = 0; i < 8; i++) {
            int m = m0 + ty * 8 + i;
            float* p = C + (size_t)m * N + n_base;
            float4 s0 = {acc[i][0] + bb[0], acc[i][1] + bb[1], acc[i][2] + bb[2], acc[i][3] + bb[3]};
            float4 s1 = {acc[i][4] + bb[4], acc[i][5] + bb[5], acc[i][6] + bb[6], acc[i][7] + bb[7]};
            *(float4*)p = s0; *(float4*)(p + 4) = s1;
        }
    } else if (MODE == 1) {
        int h = n_base >> 6, dh0 = n_base & 63;
        #pragma unroll
        for (int i = 0; i < 8; i++) {
            int l = m0 + ty * 8 + i;
            float* p = g_pos + ((size_t)((h << 10) + l)) * DH_ + dh0;
            float4 s0 = {acc[i][0], acc[i][1], acc[i][2], acc[i][3]};
            float4 s1 = {acc[i][4], acc[i][5], acc[i][6], acc[i][7]};
            *(float4*)p = s0; *(float4*)(p + 4) = s1;
        }
    } else {
        int sel   = n_base >> 9;
        int inner = n_base & 511;
        int h = inner >> 6, dh0 = inner & 63;
        float* dst = (sel == 0) ? g_q : (sel == 1) ? g_k : g_v;
        float bb[8];
        #pragma unroll
        for (int j = 0; j < 8; j++) bb[j] = bias[n_base + j];
        #pragma unroll
        for (int i = 0; i < 8; i++) {
            int m = m0 + ty * 8 + i;
            int b = m >> 10, l = m & 1023;
            float* p = dst + ((size_t)(((b << 3) + h) << 10) + l) * DH_ + dh0;
            float4 s0 = {acc[i][0] + bb[0], acc[i][1] + bb[1], acc[i][2] + bb[2], acc[i][3] + bb[3]};
            float4 s1 = {acc[i][4] + bb[4], acc[i][5] + bb[5], acc[i][6] + bb[6], acc[i][7] + bb[7]};
            *(float4*)p = s0; *(float4*)(p + 4) = s1;
        }
    }
}

// ---------------- kplus = k + pos (in place); c = u.k + v.pos ----------------
__global__ void __launch_bounds__(256) kplusc_kernel(const float* __restrict__ u,
                                                     const float* __restrict__ v)
{
    int warp = threadIdx.x >> 5, lane = threadIdx.x & 31;
    int gw = blockIdx.x * 8 + warp;       // 0 .. B*H*L-1
    int bh = gw >> 10;
    int m  = gw & 1023;
    int h  = bh & 7;
    size_t base  = ((size_t)(bh << 10) + m) * DH_;
    size_t pbase = ((size_t)(h  << 10) + m) * DH_;
    float k0 = g_k[base + lane],       k1 = g_k[base + lane + 32];
    float p0 = g_pos[pbase + lane],    p1 = g_pos[pbase + lane + 32];
    g_k[base + lane]      = k0 + p0;
    g_k[base + lane + 32] = k1 + p1;
    float cp = u[h * DH_ + lane] * k0 + u[h * DH_ + lane + 32] * k1
             + v[h * DH_ + lane] * p0 + v[h * DH_ + lane + 32] * p1;
    #pragma unroll
    for (int o = 16; o > 0; o >>= 1) cp += __shfl_xor_sync(0xffffffffu, cp, o);
    if (lane == 0) g_c[gw] = cp;
}

// ---------------- flash attention: S = q @ kplus^T + c, online softmax, O = P @ v ----------------
// block = 256 threads (8 warps), tile 64 queries x 64 keys, Dh=64.
// smem: q[64][64] | kp transposed [64][66] (reused for P [64][66]) | v[64][64]
#define KP_STRIDE 66
#define FLASH_SMEM ((4096 + 64*KP_STRIDE + 4096) * 4)

__global__ void __launch_bounds__(256) flash_kernel()
{
    extern __shared__ float sm[];
    float* q_s  = sm;                       // 64*64
    float* kp_s = sm + 4096;                // 64*66 (transposed [dh][col]; reused as P [row][m])
    float* v_s  = sm + 4096 + 64 * KP_STRIDE; // 64*64

    int bh = blockIdx.y;
    int qt = blockIdx.x;
    int tid = threadIdx.x, warp = tid >> 5, lane = tid & 31;
    int r0 = warp * 8, c0 = lane * 2;
    int b = bh >> 3, h = bh & 7;

    const float* qg = g_q + ((size_t)(bh << 10) + qt * 64) * DH_;
    #pragma unroll
    for (int i = 0; i < 4; i++) {
        int idx = tid + i * 256;
        int row = idx >> 4, col = (idx & 15) << 2;
        *(float4*)&q_s[row * 64 + col] = *(const float4*)&qg[row * 64 + col];
    }

    float mi[8], li[8], O[8][2];
    #pragma unroll
    for (int r = 0; r < 8; r++) { mi[r] = -1e30f; li[r] = 0.0f; O[r][0] = 0.0f; O[r][1] = 0.0f; }

    for (int kt = 0; kt < 16; kt++) {
        __syncthreads();      // previous PV reads of kp_s / v_s complete
        const float* kg = g_k + ((size_t)(bh << 10) + kt * 64) * DH_;
        const float* vg = g_v + ((size_t)(bh << 10) + kt * 64) * DH_;
        #pragma unroll
        for (int i = 0; i < 4; i++) {
            int idx = tid + i * 256;
            int row = idx >> 4, col = (idx & 15) << 2;
            float4 kk = *(const float4*)&kg[row * 64 + col];
            kp_s[(col + 0) * KP_STRIDE + row] = kk.x;
            kp_s[(col + 1) * KP_STRIDE + row] = kk.y;
            kp_s[(col + 2) * KP_STRIDE + row] = kk.z;
            kp_s[(col + 3) * KP_STRIDE + row] = kk.w;
            *(float4*)&v_s[row * 64 + col] = *(const float4*)&vg[row * 64 + col];
        }
        float c0v = g_c[(bh << 10) + kt * 64 + c0];
        float c1v = g_c[(bh << 10) + kt * 64 + c0 + 1];
        __syncthreads();

        float S[8][2];
        #pragma unroll
        for (int r = 0; r < 8; r++) { S[r][0] = c0v; S[r][1] = c1v; }

        #pragma unroll 4
        for (int dh = 0; dh < 64; dh++) {
            float2 kpv = *(const float2*)&kp_s[dh * KP_STRIDE + c0];
            #pragma unroll
            for (int r = 0; r < 8; r++) {
                float qv = q_s[(r0 + r) * 64 + dh];
                S[r][0] += qv * kpv.x;
                S[r][1] += qv * kpv.y;
            }
        }

        // online softmax (scale = Dh^-0.5 = 0.125)
        #pragma unroll
        for (int r = 0; r < 8; r++) {
            float s0 = S[r][0] * 0.125f, s1 = S[r][1] * 0.125f;
            float mx = fmaxf(s0, s1);
            #pragma unroll
            for (int o = 16; o > 0; o >>= 1) mx = fmaxf(mx, __shfl_xor_sync(0xffffffffu, mx, o));
            float mnew = fmaxf(mi[r], mx);
            float corr = __expf(mi[r] - mnew);
            float p0 = __expf(s0 - mnew), p1 = __expf(s1 - mnew);
            float ls = p0 + p1;
            #pragma unroll
            for (int o = 16; o > 0; o >>= 1) ls += __shfl_xor_sync(0xffffffffu, ls, o);
            li[r] = li[r] * corr + ls;
            mi[r] = mnew;
            O[r][0] *= corr; O[r][1] *= corr;
            S[r][0] = p0; S[r][1] = p1;
        }

        __syncthreads();      // kp_s score reads complete; reuse region for P
        #pragma unroll
        for (int r = 0; r < 8; r++) {
            float2 pp; pp.x = S[r][0]; pp.y = S[r][1];
            *(float2*)&kp_s[(r0 + r) * KP_STRIDE + c0] = pp;
        }
        __syncthreads();

        #pragma unroll 4
        for (int m = 0; m < 64; m++) {
            float2 vv = *(const float2*)&v_s[m * 64 + c0];
            #pragma unroll
            for (int r = 0; r < 8; r++) {
                float p = kp_s[(r0 + r) * KP_STRIDE + m];
                O[r][0] += p * vv.x;
                O[r][1] += p * vv.y;
            }
        }
    }

    #pragma unroll
    for (int r = 0; r < 8; r++) {
        float inv = 1.0f / li[r];
        int row = qt * 64 + r0 + r;
        float2 ov; ov.x = O[r][0] * inv; ov.y = O[r][1] * inv;
        *(float2*)&g_ctx[((size_t)(b << 10) + row) * D_ + h * DH_ + c0] = ov;
    }
}

// ---------------- launch ----------------
extern "C" void kernel_launch(void* const* d_in, const int* in_sizes, int n_in,
                              void* d_out, int out_size)
{
    const float* x      = (const float*)d_in[0];
    const float* gamma  = (const float*)d_in[1];
    const float* beta   = (const float*)d_in[2];
    const float* w_qkv  = (const float*)d_in[3];
    const float* b_qkv  = (const float*)d_in[4];
    const float* w_pos  = (const float*)d_in[5];
    const float* w_out  = (const float*)d_in[6];
    const float* b_out  = (const float*)d_in[7];
    const float* u_bias = (const float*)d_in[8];
    const float* v_bias = (const float*)d_in[9];
    float* out = (float*)d_out;

    cudaFuncSetAttribute(flash_kernel, cudaFuncAttributeMaxDynamicSharedMemorySize, FLASH_SMEM);

    // 1. LayerNorm
    ln_kernel<<<B_ * L_, 128>>>(x, gamma, beta);
    // 2. sinusoid table
    pe_kernel<<<L_, 256>>>();
    // 3. pos = pe @ w_pos^T  (M=1024, N=512, K=512)
    gemm_kernel<1><<<dim3(4, 8), 256>>>(w_pos, nullptr, nullptr, L_, INNER_, D_);
    // 4. qkv = xn @ w_qkv^T + b_qkv  (M=8192, N=1536, K=512), split to q/k/v head layout
    gemm_kernel<2><<<dim3(12, 64), 256>>>(w_qkv, b_qkv, nullptr, B_ * L_, 3 * INNER_, D_);
    // 5. kplus = k + pos (in place), c = u.k + v.pos
    kplusc_kernel<<<(BH_ * L_) / 8, 256>>>(u_bias, v_bias);
    // 6. flash attention -> ctx
    flash_kernel<<<dim3(16, BH_), 256, FLASH_SMEM>>>();
    // 7. out = ctx @ w_out^T + b_out  (M=8192, N=512, K=512)
    gemm_kernel<0><<<dim3(4, 64), 256>>>(w_out, b_out, out, B_ * L_, D_, D_);
}